// round 9
// baseline (speedup 1.0000x reference)
#include <cuda_runtime.h>
#include <cuda_fp16.h>
#include <cstdint>

// Problem constants
#define BB 8
#define TT 256
#define UU 128
#define HH 512
#define II 640
#define VV 1024

// Scratch (no cudaMalloc allowed)
__device__ float  g_enc_proj[BB * TT * II];   // (2048, 640) fp32
__device__ float  g_dec_proj[BB * UU * II];   // (1024, 640) fp32
__device__ __half g_w_half[VV * II];          // W^T fp16 [v][k]

__device__ __forceinline__ uint32_t smem_u32(const void* p) {
    uint32_t a;
    asm("{ .reg .u64 t; cvta.to.shared.u64 t, %1; cvt.u32.u64 %0, t; }"
        : "=r"(a) : "l"(p));
    return a;
}

// HW tanh: single MUFU op (sm_75+), rel err ~2^-11 — below the fp16
// quantization applied right after.
__device__ __forceinline__ float tanh_hw(float x) {
    float y;
    asm("tanh.approx.f32 %0, %1;" : "=f"(y) : "f"(x));
    return y;
}

__device__ __forceinline__ void mma16816(float* c,
    uint32_t a0, uint32_t a1, uint32_t a2, uint32_t a3,
    uint32_t b0, uint32_t b1)
{
    asm volatile(
        "mma.sync.aligned.m16n8k16.row.col.f32.f16.f16.f32 "
        "{%0,%1,%2,%3}, {%4,%5,%6,%7}, {%8,%9}, {%0,%1,%2,%3};"
        : "+f"(c[0]), "+f"(c[1]), "+f"(c[2]), "+f"(c[3])
        : "r"(a0), "r"(a1), "r"(a2), "r"(a3), "r"(b0), "r"(b1));
}

__device__ __forceinline__ void ldsm4(uint32_t* r, uint32_t addr) {
    asm volatile("ldmatrix.sync.aligned.m8n8.x4.shared.b16 {%0,%1,%2,%3}, [%4];"
        : "=r"(r[0]), "=r"(r[1]), "=r"(r[2]), "=r"(r[3]) : "r"(addr));
}

__device__ __forceinline__ void cp_async16(uint32_t dst, const void* src) {
    asm volatile("cp.async.ca.shared.global [%0], [%1], 16;"
                 :: "r"(dst), "l"(src) : "memory");
}
#define CP_COMMIT() asm volatile("cp.async.commit_group;" ::: "memory")
#define CP_WAIT1()  asm volatile("cp.async.wait_group 1;" ::: "memory")

// ---------------------------------------------------------------------------
// Kernel 1: merged prep. Blocks [0,960): enc/dec projections (32x64 tiles).
// Blocks [960, 2240): dense_w transpose+fp16 (memory-bound, fills idle SMs).
// ---------------------------------------------------------------------------
__global__ __launch_bounds__(128) void prep_kernel(
    const float* __restrict__ enc_h, const float* __restrict__ dec_h,
    const float* __restrict__ enc_w, const float* __restrict__ enc_b,
    const float* __restrict__ dec_w, const float* __restrict__ dec_b,
    const float* __restrict__ dense_w)
{
    const int bid = blockIdx.x;

    if (bid >= 960) {
        // ---- wsplit: dense_w (640x1024 [k][v]) -> fp16 W^T [v][k] ----
        int idx4 = (bid - 960) * 128 + threadIdx.x;   // 0..163839
        int base = idx4 * 4;
        int k = base >> 10;
        int v = base & 1023;
        float4 x = *(const float4*)(dense_w + base);   // 4 consecutive v, same k
        g_w_half[(size_t)(v + 0) * II + k] = __float2half(x.x);
        g_w_half[(size_t)(v + 1) * II + k] = __float2half(x.y);
        g_w_half[(size_t)(v + 2) * II + k] = __float2half(x.z);
        g_w_half[(size_t)(v + 3) * II + k] = __float2half(x.w);
        return;
    }

    // ---- projections ----
    __shared__ float As[16][36];
    __shared__ float Bs[16][64];

    const int bx = bid % 10;
    const int by = bid / 10;
    const int r0 = by * 32;
    const int n0 = bx * 64;

    const float* in; const float* w; const float* bias; float* outp;
    if (r0 < BB * TT) {
        in = enc_h + (size_t)r0 * HH; w = enc_w; bias = enc_b;
        outp = g_enc_proj + (size_t)r0 * II;
    } else {
        const int r = r0 - BB * TT;
        in = dec_h + (size_t)r * HH; w = dec_w; bias = dec_b;
        outp = g_dec_proj + (size_t)r * II;
    }

    const int t  = threadIdx.x;
    const int tx = t & 15, ty = t >> 4;
    const int a_row = t >> 2;
    const int a_k4  = (t & 3) * 4;
    const int b_kk  = t >> 4;
    const int b_j4  = (t & 15) * 4;

    float acc[4][4] = {};
    for (int k0 = 0; k0 < HH; k0 += 16) {
        float4 av = *(const float4*)(in + (size_t)a_row * HH + k0 + a_k4);
        As[a_k4 + 0][a_row] = av.x;
        As[a_k4 + 1][a_row] = av.y;
        As[a_k4 + 2][a_row] = av.z;
        As[a_k4 + 3][a_row] = av.w;
        #pragma unroll
        for (int j = 0; j < 2; j++)
            *(float4*)&Bs[b_kk + j * 8][b_j4] =
                *(const float4*)(w + (size_t)(k0 + b_kk + j * 8) * II + n0 + b_j4);
        __syncthreads();
        #pragma unroll
        for (int kk = 0; kk < 16; kk++) {
            float4 a4 = *(const float4*)&As[kk][ty * 4];
            float4 b4 = *(const float4*)&Bs[kk][tx * 4];
            float a[4] = {a4.x, a4.y, a4.z, a4.w};
            float bw[4] = {b4.x, b4.y, b4.z, b4.w};
            #pragma unroll
            for (int i = 0; i < 4; i++)
                #pragma unroll
                for (int j = 0; j < 4; j++)
                    acc[i][j] = fmaf(a[i], bw[j], acc[i][j]);
        }
        __syncthreads();
    }
    float4 bv = *(const float4*)(bias + n0 + tx * 4);
    float bb[4] = {bv.x, bv.y, bv.z, bv.w};
    #pragma unroll
    for (int i = 0; i < 4; i++) {
        float4 o;
        o.x = acc[i][0] + bb[0]; o.y = acc[i][1] + bb[1];
        o.z = acc[i][2] + bb[2]; o.w = acc[i][3] + bb[3];
        *(float4*)(outp + (size_t)(ty * 4 + i) * II + n0 + tx * 4) = o;
    }
}

// ---------------------------------------------------------------------------
// Kernel 2: fused joint GEMM, 2 CTAs/SM (structure proven in R8).
// CTA = 64 u-rows x full V=1024. 256 thr / 8 warps, warp tile 32x32.
// A panel 64x640 fp16, XOR-16B swizzled (stride 1280) -> 80KB.
// B: 3-stage cp.async pipeline, 128-row n-tiles, 10KB/stage.
// ---------------------------------------------------------------------------
#define A_STRIDE 1280                 // 640*2, no pad; XOR swizzle instead
#define A_PANEL  (64 * A_STRIDE)      // 81920
#define B_STRIDE 80                   // 32*2 + 16B pad (20 words)
#define B_CHUNK  (128 * B_STRIDE)     // 10240
#define NSTAGE   3
#define DYN_SMEM (A_PANEL + NSTAGE * B_CHUNK)  // 112640
#define NCHUNK   160                  // 8 n-tiles * 20 k-chunks

__global__ __launch_bounds__(256, 2) void joint_mma_kernel(
    const float* __restrict__ dense_b, float* __restrict__ out)
{
    extern __shared__ __align__(16) char smem[];
    const uint32_t smb   = smem_u32(smem);
    const uint32_t smb_B = smb + A_PANEL;

    const int tid  = threadIdx.x;
    const int lane = tid & 31;
    const int wid  = tid >> 5;
    const int warp_m = wid & 1;    // 0..1 (M halves of 32)
    const int warp_n = wid >> 1;   // 0..3 (N quarters of 32 within 128-tile)

    const int bt    = blockIdx.x >> 1;
    const int urow0 = (blockIdx.x & 1) * 64;
    const int b     = bt >> 8;

    const float* __restrict__ encp = g_enc_proj + (size_t)bt * II;
    const float* __restrict__ decp = g_dec_proj + (size_t)(b * UU + urow0) * II;

    // ---- per-thread cp.async constants ----
    const int nl0 = tid >> 2;          // 0..63 (+64 for second)
    const int q0  = tid & 3;
    const __half* wt0 = g_w_half + (size_t)nl0 * II + q0 * 8;
    const uint32_t d0 = (uint32_t)nl0 * B_STRIDE + q0 * 16;

    // Prologue BEFORE phase 1: chunks 0, 1 into stages 0, 1
    cp_async16(smb_B + d0,                      wt0);
    cp_async16(smb_B + d0 + 64 * B_STRIDE,      wt0 + (size_t)64 * II);
    CP_COMMIT();
    cp_async16(smb_B + B_CHUNK + d0,                 wt0 + 32);
    cp_async16(smb_B + B_CHUNK + d0 + 64 * B_STRIDE, wt0 + (size_t)64 * II + 32);
    CP_COMMIT();

    // ---- Phase 1: A panel 64x640 tanh+fp16, XOR-swizzled stores ----
    {
        const int row = tid >> 2;          // 0..63
        const int kq  = tid & 3;
        const int rsw = row & 7;
        char* rowp = smem + row * A_STRIDE;
        const float* dp = decp + (size_t)row * II;
        #pragma unroll 1
        for (int seg = 0; seg < 10; seg++) {
            const int k = seg * 64 + kq * 16;
            float s[16];
            #pragma unroll
            for (int q = 0; q < 4; q++) {
                float4 d = *(const float4*)(dp + k + q * 4);
                float4 e = *(const float4*)(encp + k + q * 4);
                s[q * 4 + 0] = tanh_hw(d.x + e.x);
                s[q * 4 + 1] = tanh_hw(d.y + e.y);
                s[q * 4 + 2] = tanh_hw(d.z + e.z);
                s[q * 4 + 3] = tanh_hw(d.w + e.w);
            }
            uint32_t h[8];
            #pragma unroll
            for (int q = 0; q < 8; q++) {
                __half2 hh = __floats2half2_rn(s[2 * q], s[2 * q + 1]);
                h[q] = *reinterpret_cast<uint32_t*>(&hh);
            }
            const int ub = seg * 8 + kq * 2;     // 16B unit index
            *(uint4*)(rowp + (((ub + 0) ^ rsw) << 4)) = make_uint4(h[0], h[1], h[2], h[3]);
            *(uint4*)(rowp + (((ub + 1) ^ rsw) << 4)) = make_uint4(h[4], h[5], h[6], h[7]);
        }
    }

    // ---- per-lane ldmatrix bases ----
    const int a_row = warp_m * 32 + (lane & 15);
    const uint32_t A_row0 = smb + (uint32_t)a_row * A_STRIDE;
    const uint32_t A_row1 = A_row0 + 16 * A_STRIDE;
    const int a_rsw0 = a_row & 7;
    const int a_rsw1 = (a_row + 16) & 7;
    const int a_ulane = (lane >> 4);
    const uint32_t B_lane = (uint32_t)(warp_n * 32 + ((lane >> 4) << 3) + (lane & 7)) * B_STRIDE
                          + (uint32_t)((lane >> 3) & 1) * 16;

    float acc[2][4][4];
    #pragma unroll
    for (int i = 0; i < 2; i++)
        #pragma unroll
        for (int j = 0; j < 4; j++)
            #pragma unroll
            for (int l = 0; l < 4; l++) acc[i][j][l] = 0.0f;

    CP_WAIT1();        // chunk 0 landed
    __syncthreads();   // A panel + B chunk 0 ready

    // wrap-around loop state (no div/mod)
    const __half* wp = wt0 + 64;   // prefetch source for chunk 2
    int pk     = 2;
    int pstage = 2;
    int stage  = 0;
    int kc     = 0;
    int n0cur  = 0;
    int remain = NCHUNK - 2;

    #pragma unroll 1
    for (int c = 0; c < NCHUNK; c++) {
        if (remain > 0) {
            remain--;
            const uint32_t dstb = smb_B + (uint32_t)pstage * B_CHUNK + d0;
            cp_async16(dstb,                 wp);
            cp_async16(dstb + 64 * B_STRIDE, wp + (size_t)64 * II);
            wp += 32;
            if (++pk == 20) { pk = 0; wp += (size_t)128 * II - 640; }
            if (++pstage == NSTAGE) pstage = 0;
        }
        CP_COMMIT();

        // ---- MMA on chunk c ----
        const uint32_t Bbase = smb_B + (uint32_t)stage * B_CHUNK + B_lane;
        const int ub = kc * 4 + a_ulane;
        #pragma unroll
        for (int ks = 0; ks < 2; ks++) {
            uint32_t a0[4], a1[4];
            const int u = ub + ks * 2;
            ldsm4(a0, A_row0 + (uint32_t)((u ^ a_rsw0) << 4));
            ldsm4(a1, A_row1 + (uint32_t)((u ^ a_rsw1) << 4));
            uint32_t bf[2][4];
            #pragma unroll
            for (int ntp = 0; ntp < 2; ntp++)
                ldsm4(bf[ntp], Bbase + ntp * (16 * B_STRIDE) + ks * 32);
            #pragma unroll
            for (int ntp = 0; ntp < 2; ntp++) {
                mma16816(acc[0][2 * ntp + 0], a0[0], a0[1], a0[2], a0[3], bf[ntp][0], bf[ntp][1]);
                mma16816(acc[0][2 * ntp + 1], a0[0], a0[1], a0[2], a0[3], bf[ntp][2], bf[ntp][3]);
                mma16816(acc[1][2 * ntp + 0], a1[0], a1[1], a1[2], a1[3], bf[ntp][0], bf[ntp][1]);
                mma16816(acc[1][2 * ntp + 1], a1[0], a1[1], a1[2], a1[3], bf[ntp][2], bf[ntp][3]);
            }
        }

        // ---- epilogue at n-tile boundary ----
        if (kc == 19) {
            #pragma unroll
            for (int mt = 0; mt < 2; mt++) {
                const int r = warp_m * 32 + mt * 16 + (lane >> 2);
                float* o0 = out + ((size_t)bt * 128 + urow0 + r) * VV;
                #pragma unroll
                for (int nt = 0; nt < 4; nt++) {
                    const int col = n0cur + warp_n * 32 + nt * 8 + (lane & 3) * 2;
                    float2 bb = *(const float2*)(dense_b + col);
                    float2 v0 = make_float2(acc[mt][nt][0] + bb.x, acc[mt][nt][1] + bb.y);
                    float2 v1 = make_float2(acc[mt][nt][2] + bb.x, acc[mt][nt][3] + bb.y);
                    *(float2*)(o0 + col) = v0;
                    *(float2*)(o0 + (size_t)8 * VV + col) = v1;
                    #pragma unroll
                    for (int l = 0; l < 4; l++) acc[mt][nt][l] = 0.0f;
                }
            }
            n0cur += 128;
            kc = -1;
        }
        kc++;
        if (++stage == NSTAGE) stage = 0;

        CP_WAIT1();
        __syncthreads();
    }
}

// ---------------------------------------------------------------------------
extern "C" void kernel_launch(void* const* d_in, const int* in_sizes, int n_in,
                              void* d_out, int out_size) {
    const float* enc_h   = (const float*)d_in[0];
    const float* dec_h   = (const float*)d_in[1];
    const float* enc_w   = (const float*)d_in[2];
    const float* enc_b   = (const float*)d_in[3];
    const float* dec_w   = (const float*)d_in[4];
    const float* dec_b   = (const float*)d_in[5];
    const float* dense_w = (const float*)d_in[6];
    const float* dense_b = (const float*)d_in[7];
    float* out = (float*)d_out;

    static bool attr_set = false;
    if (!attr_set) {
        cudaFuncSetAttribute(joint_mma_kernel,
                             cudaFuncAttributeMaxDynamicSharedMemorySize, DYN_SMEM);
        attr_set = true;
    }

    // merged prep: 960 proj blocks + 1280 wsplit blocks, overlap on-chip
    prep_kernel<<<2240, 128>>>(enc_h, dec_h, enc_w, enc_b, dec_w, dec_b, dense_w);
    // 4096 CTAs: (bt, u-half); each covers full V. 2 CTAs resident per SM.
    joint_mma_kernel<<<4096, 256, DYN_SMEM>>>(dense_b, out);
}

// round 10
// speedup vs baseline: 1.0696x; 1.0696x over previous
#include <cuda_runtime.h>
#include <cuda_fp16.h>
#include <cstdint>

// Problem constants
#define BB 8
#define TT 256
#define UU 128
#define HH 512
#define II 640
#define VV 1024

// Scratch (no cudaMalloc allowed)
__device__ float  g_enc_proj[BB * TT * II];   // (2048, 640) fp32
__device__ float  g_dec_proj[BB * UU * II];   // (1024, 640) fp32
__device__ __half g_w_half[VV * II];          // W^T fp16 [v][k]

__device__ __forceinline__ uint32_t smem_u32(const void* p) {
    uint32_t a;
    asm("{ .reg .u64 t; cvta.to.shared.u64 t, %1; cvt.u32.u64 %0, t; }"
        : "=r"(a) : "l"(p));
    return a;
}

// HW tanh: single MUFU op, rel err ~2^-11 (below the fp16 quantization)
__device__ __forceinline__ float tanh_hw(float x) {
    float y;
    asm("tanh.approx.f32 %0, %1;" : "=f"(y) : "f"(x));
    return y;
}

__device__ __forceinline__ void mma16816(float* c,
    uint32_t a0, uint32_t a1, uint32_t a2, uint32_t a3,
    uint32_t b0, uint32_t b1)
{
    asm volatile(
        "mma.sync.aligned.m16n8k16.row.col.f32.f16.f16.f32 "
        "{%0,%1,%2,%3}, {%4,%5,%6,%7}, {%8,%9}, {%0,%1,%2,%3};"
        : "+f"(c[0]), "+f"(c[1]), "+f"(c[2]), "+f"(c[3])
        : "r"(a0), "r"(a1), "r"(a2), "r"(a3), "r"(b0), "r"(b1));
}

__device__ __forceinline__ void ldsm4(uint32_t* r, uint32_t addr) {
    asm volatile("ldmatrix.sync.aligned.m8n8.x4.shared.b16 {%0,%1,%2,%3}, [%4];"
        : "=r"(r[0]), "=r"(r[1]), "=r"(r[2]), "=r"(r[3]) : "r"(addr));
}

// .cg: bypass L1 allocation (W bytes are single-use per CTA)
__device__ __forceinline__ void cp_async16(uint32_t dst, const void* src) {
    asm volatile("cp.async.cg.shared.global [%0], [%1], 16;"
                 :: "r"(dst), "l"(src) : "memory");
}
#define CP_COMMIT() asm volatile("cp.async.commit_group;" ::: "memory")
#define CP_WAIT0()  asm volatile("cp.async.wait_group 0;" ::: "memory")

// ---------------------------------------------------------------------------
// Kernel 1: enc/dec projections. 32x64 tiles, 128 thr, grid 960.
// ---------------------------------------------------------------------------
__global__ __launch_bounds__(128) void proj_kernel(
    const float* __restrict__ enc_h, const float* __restrict__ dec_h,
    const float* __restrict__ enc_w, const float* __restrict__ enc_b,
    const float* __restrict__ dec_w, const float* __restrict__ dec_b)
{
    __shared__ float As[16][36];
    __shared__ float Bs[16][64];

    const int r0 = blockIdx.y * 32;
    const int n0 = blockIdx.x * 64;

    const float* in; const float* w; const float* bias; float* outp;
    if (r0 < BB * TT) {
        in = enc_h + (size_t)r0 * HH; w = enc_w; bias = enc_b;
        outp = g_enc_proj + (size_t)r0 * II;
    } else {
        const int r = r0 - BB * TT;
        in = dec_h + (size_t)r * HH; w = dec_w; bias = dec_b;
        outp = g_dec_proj + (size_t)r * II;
    }

    const int t  = threadIdx.x;
    const int tx = t & 15, ty = t >> 4;
    const int a_row = t >> 2;
    const int a_k4  = (t & 3) * 4;
    const int b_kk  = t >> 4;
    const int b_j4  = (t & 15) * 4;

    float acc[4][4] = {};
    for (int k0 = 0; k0 < HH; k0 += 16) {
        float4 av = *(const float4*)(in + (size_t)a_row * HH + k0 + a_k4);
        As[a_k4 + 0][a_row] = av.x;
        As[a_k4 + 1][a_row] = av.y;
        As[a_k4 + 2][a_row] = av.z;
        As[a_k4 + 3][a_row] = av.w;
        #pragma unroll
        for (int j = 0; j < 2; j++)
            *(float4*)&Bs[b_kk + j * 8][b_j4] =
                *(const float4*)(w + (size_t)(k0 + b_kk + j * 8) * II + n0 + b_j4);
        __syncthreads();
        #pragma unroll
        for (int kk = 0; kk < 16; kk++) {
            float4 a4 = *(const float4*)&As[kk][ty * 4];
            float4 b4 = *(const float4*)&Bs[kk][tx * 4];
            float a[4] = {a4.x, a4.y, a4.z, a4.w};
            float bw[4] = {b4.x, b4.y, b4.z, b4.w};
            #pragma unroll
            for (int i = 0; i < 4; i++)
                #pragma unroll
                for (int j = 0; j < 4; j++)
                    acc[i][j] = fmaf(a[i], bw[j], acc[i][j]);
        }
        __syncthreads();
    }
    float4 bv = *(const float4*)(bias + n0 + tx * 4);
    float bb[4] = {bv.x, bv.y, bv.z, bv.w};
    #pragma unroll
    for (int i = 0; i < 4; i++) {
        float4 o;
        o.x = acc[i][0] + bb[0]; o.y = acc[i][1] + bb[1];
        o.z = acc[i][2] + bb[2]; o.w = acc[i][3] + bb[3];
        *(float4*)(outp + (size_t)(ty * 4 + i) * II + n0 + tx * 4) = o;
    }
}

// ---------------------------------------------------------------------------
// Kernel 2: dense_w (640x1024 [k][v]) -> fp16 W^T [v][k], smem transpose
// for coalesced reads AND writes. Tile 32x32, 256 thr, grid 640.
// ---------------------------------------------------------------------------
__global__ __launch_bounds__(256) void wsplit_kernel(const float* __restrict__ W) {
    __shared__ float tile[32][33];
    const int v0 = (blockIdx.x & 31) * 32;
    const int k0 = (blockIdx.x >> 5) * 32;
    const int tx = threadIdx.x & 31;
    const int ty = threadIdx.x >> 5;   // 0..7
    #pragma unroll
    for (int i = 0; i < 4; i++) {
        int k = k0 + ty + i * 8;
        tile[ty + i * 8][tx] = W[(size_t)k * VV + v0 + tx];
    }
    __syncthreads();
    #pragma unroll
    for (int i = 0; i < 4; i++) {
        int v = v0 + ty + i * 8;
        g_w_half[(size_t)v * II + k0 + tx] = __float2half(tile[tx][ty + i * 8]);
    }
}

// ---------------------------------------------------------------------------
// Kernel 3: fused joint GEMM, 2 CTAs/SM, warp tile 32x64 (LDS/FLOP -25%).
// CTA = 64 u-rows x full V=1024 in 4 n-tiles of 256. 256 thr / 8 warps.
// A panel 64x640 fp16, XOR-16B swizzled (stride 1280) -> 80KB.
// B: BK=16 chunks, 2-stage cp.async.cg pipeline, 12KB/stage. Total 104KB.
// ---------------------------------------------------------------------------
#define A_STRIDE 1280                 // 640*2; XOR swizzle
#define A_PANEL  (64 * A_STRIDE)      // 81920
#define B_STRIDE 48                   // 16*2 + 16B pad (12 words; 3r%8 distinct)
#define B_CHUNK  (256 * B_STRIDE)     // 12288
#define DYN_SMEM (A_PANEL + 2 * B_CHUNK)  // 106496
#define KCH      40                   // k-chunks per n-tile (640/16)
#define NCHUNK   160                  // 4 n-tiles * 40 k-chunks

__global__ __launch_bounds__(256, 2) void joint_mma_kernel(
    const float* __restrict__ dense_b, float* __restrict__ out)
{
    extern __shared__ __align__(16) char smem[];
    const uint32_t smb   = smem_u32(smem);
    const uint32_t smb_B = smb + A_PANEL;

    const int tid  = threadIdx.x;
    const int lane = tid & 31;
    const int wid  = tid >> 5;
    const int warp_m = wid & 1;    // 0..1 (M halves of 32)
    const int warp_n = wid >> 1;   // 0..3 (N quarters of 64 within 256-tile)

    const int bt    = blockIdx.x >> 1;
    const int urow0 = (blockIdx.x & 1) * 64;
    const int b     = bt >> 8;

    const float* __restrict__ encp = g_enc_proj + (size_t)bt * II;
    const float* __restrict__ decp = g_dec_proj + (size_t)(b * UU + urow0) * II;

    // ---- per-thread cp.async constants: 2 x 16B per chunk (8KB total) ----
    const int nl0 = tid >> 1;          // 0..127 (+128 for second)
    const int q0  = tid & 1;           // 16B unit within 32B row data
    const __half* wt0 = g_w_half + (size_t)nl0 * II + q0 * 8;
    const uint32_t d0 = (uint32_t)nl0 * B_STRIDE + q0 * 16;

    // Prologue BEFORE phase 1: chunk 0 into stage 0
    cp_async16(smb_B + d0,                       wt0);
    cp_async16(smb_B + d0 + 128 * B_STRIDE,      wt0 + (size_t)128 * II);
    CP_COMMIT();

    // ---- Phase 1: A panel 64x640 tanh+fp16, XOR-swizzled stores ----
    {
        const int row = tid >> 2;          // 0..63
        const int kq  = tid & 3;
        const int rsw = row & 7;
        char* rowp = smem + row * A_STRIDE;
        const float* dp = decp + (size_t)row * II;
        #pragma unroll 1
        for (int seg = 0; seg < 10; seg++) {
            const int k = seg * 64 + kq * 16;
            float s[16];
            #pragma unroll
            for (int q = 0; q < 4; q++) {
                float4 d = *(const float4*)(dp + k + q * 4);
                float4 e = *(const float4*)(encp + k + q * 4);
                s[q * 4 + 0] = tanh_hw(d.x + e.x);
                s[q * 4 + 1] = tanh_hw(d.y + e.y);
                s[q * 4 + 2] = tanh_hw(d.z + e.z);
                s[q * 4 + 3] = tanh_hw(d.w + e.w);
            }
            uint32_t h[8];
            #pragma unroll
            for (int q = 0; q < 8; q++) {
                __half2 hh = __floats2half2_rn(s[2 * q], s[2 * q + 1]);
                h[q] = *reinterpret_cast<uint32_t*>(&hh);
            }
            const int ub = seg * 8 + kq * 2;     // 16B unit index
            *(uint4*)(rowp + (((ub + 0) ^ rsw) << 4)) = make_uint4(h[0], h[1], h[2], h[3]);
            *(uint4*)(rowp + (((ub + 1) ^ rsw) << 4)) = make_uint4(h[4], h[5], h[6], h[7]);
        }
    }

    // ---- per-lane ldmatrix bases ----
    const int a_row = warp_m * 32 + (lane & 15);
    const uint32_t A_row0 = smb + (uint32_t)a_row * A_STRIDE;
    const uint32_t A_row1 = A_row0 + 16 * A_STRIDE;
    const int a_rsw0 = a_row & 7;
    const int a_rsw1 = (a_row + 16) & 7;
    const int a_ulane = (lane >> 4);
    // B: 16 n-rows x 16 k per ldsm4; ntp strides 16 rows (N_w = 64).
    const uint32_t B_lane = (uint32_t)(warp_n * 64 + ((lane >> 4) << 3) + (lane & 7)) * B_STRIDE
                          + (uint32_t)((lane >> 3) & 1) * 16;

    float acc[2][8][4];
    #pragma unroll
    for (int i = 0; i < 2; i++)
        #pragma unroll
        for (int j = 0; j < 8; j++)
            #pragma unroll
            for (int l = 0; l < 4; l++) acc[i][j][l] = 0.0f;

    CP_WAIT0();        // chunk 0 landed (during phase 1)
    __syncthreads();   // A panel + B chunk 0 ready

    // wrap-around loop state (no div/mod)
    const __half* wp = wt0 + 16;   // prefetch source for chunk 1
    int pk     = 1;                // prefetch k-chunk within n-tile
    int pstage = 1;
    int stage  = 0;
    int kc     = 0;                // k-chunk of current chunk
    int n0cur  = 0;                // current n-tile base column
    int remain = NCHUNK - 1;

    #pragma unroll 1
    for (int c = 0; c < NCHUNK; c++) {
        // prefetch chunk c+1 into the other stage
        if (remain > 0) {
            remain--;
            const uint32_t dstb = smb_B + (uint32_t)pstage * B_CHUNK + d0;
            cp_async16(dstb,                  wp);
            cp_async16(dstb + 128 * B_STRIDE, wp + (size_t)128 * II);
            wp += 16;
            if (++pk == KCH) { pk = 0; wp += (size_t)256 * II - 640; }
            pstage ^= 1;
        }
        CP_COMMIT();

        // ---- MMA on chunk c (one k16 step, warp tile 32x64) ----
        const uint32_t Bbase = smb_B + (uint32_t)stage * B_CHUNK + B_lane;
        const int u = kc * 2 + a_ulane;
        uint32_t a0[4], a1[4];
        ldsm4(a0, A_row0 + (uint32_t)((u ^ a_rsw0) << 4));
        ldsm4(a1, A_row1 + (uint32_t)((u ^ a_rsw1) << 4));
        uint32_t bf[4][4];
        #pragma unroll
        for (int ntp = 0; ntp < 4; ntp++)
            ldsm4(bf[ntp], Bbase + ntp * (16 * B_STRIDE));
        #pragma unroll
        for (int ntp = 0; ntp < 4; ntp++) {
            mma16816(acc[0][2 * ntp + 0], a0[0], a0[1], a0[2], a0[3], bf[ntp][0], bf[ntp][1]);
            mma16816(acc[0][2 * ntp + 1], a0[0], a0[1], a0[2], a0[3], bf[ntp][2], bf[ntp][3]);
            mma16816(acc[1][2 * ntp + 0], a1[0], a1[1], a1[2], a1[3], bf[ntp][0], bf[ntp][1]);
            mma16816(acc[1][2 * ntp + 1], a1[0], a1[1], a1[2], a1[3], bf[ntp][2], bf[ntp][3]);
        }

        // ---- epilogue at n-tile boundary ----
        if (kc == KCH - 1) {
            #pragma unroll
            for (int mt = 0; mt < 2; mt++) {
                const int r = warp_m * 32 + mt * 16 + (lane >> 2);
                float* o0 = out + ((size_t)bt * 128 + urow0 + r) * VV;
                #pragma unroll
                for (int nt = 0; nt < 8; nt++) {
                    const int col = n0cur + warp_n * 64 + nt * 8 + (lane & 3) * 2;
                    float2 bb = *(const float2*)(dense_b + col);
                    float2 v0 = make_float2(acc[mt][nt][0] + bb.x, acc[mt][nt][1] + bb.y);
                    float2 v1 = make_float2(acc[mt][nt][2] + bb.x, acc[mt][nt][3] + bb.y);
                    *(float2*)(o0 + col) = v0;
                    *(float2*)(o0 + (size_t)8 * VV + col) = v1;
                    #pragma unroll
                    for (int l = 0; l < 4; l++) acc[mt][nt][l] = 0.0f;
                }
            }
            n0cur += 256;
            kc = -1;
        }
        kc++;
        stage ^= 1;

        CP_WAIT0();      // chunk c+1 landed
        __syncthreads(); // publish + protect stage reuse
    }
}

// ---------------------------------------------------------------------------
extern "C" void kernel_launch(void* const* d_in, const int* in_sizes, int n_in,
                              void* d_out, int out_size) {
    const float* enc_h   = (const float*)d_in[0];
    const float* dec_h   = (const float*)d_in[1];
    const float* enc_w   = (const float*)d_in[2];
    const float* enc_b   = (const float*)d_in[3];
    const float* dec_w   = (const float*)d_in[4];
    const float* dec_b   = (const float*)d_in[5];
    const float* dense_w = (const float*)d_in[6];
    const float* dense_b = (const float*)d_in[7];
    float* out = (float*)d_out;

    static bool attr_set = false;
    if (!attr_set) {
        cudaFuncSetAttribute(joint_mma_kernel,
                             cudaFuncAttributeMaxDynamicSharedMemorySize, DYN_SMEM);
        attr_set = true;
    }

    proj_kernel<<<dim3(10, 96), 128>>>(enc_h, dec_h, enc_w, enc_b, dec_w, dec_b);
    wsplit_kernel<<<640, 256>>>(dense_w);
    // 4096 CTAs: (bt, u-half); each covers full V. 2 CTAs resident per SM.
    joint_mma_kernel<<<4096, 256, DYN_SMEM>>>(dense_b, out);
}